// round 5
// baseline (speedup 1.0000x reference)
#include <cuda_runtime.h>
#include <cstdint>

#define K0     16
#define DIN    4096
#define DOUT   4096
#define NROWS  8192
#define TPB    128
#define CPT    2                    // columns per thread (one f32x2 pair)
#define CPB    (TPB * CPT)          // 256 columns per block
#define RPB    32                   // rows per tile
#define NTILES (NROWS / RPB)        // 256
#define YBLKS  64                   // 4 tiles per block, grid 16x64=1024 blks

// ---- packed f32x2 helpers (Blackwell FFMA2 path, PTX-only) ----
__device__ __forceinline__ unsigned long long ffma2(unsigned long long a,
                                                    unsigned long long b,
                                                    unsigned long long c) {
    unsigned long long d;
    asm("fma.rn.f32x2 %0, %1, %2, %3;" : "=l"(d) : "l"(a), "l"(b), "l"(c));
    return d;
}

__device__ __forceinline__ unsigned long long pack2(float lo, float hi) {
    unsigned long long r;
    asm("mov.b64 %0, {%1, %2};" : "=l"(r) : "f"(lo), "f"(hi));
    return r;
}

// out[r,o] = c + sum_{k<16} x[r,k]*W[o,k]
// (tstat >= 0 > TAU so the reference mask is identically "active".)
// Column-paired accumulation: thread's accumulator lanes are the two adjacent
// output columns; x[k] is pre-duplicated into both lanes in smem, so the
// accumulator is stored directly (no horizontal add), initialized to (c,c).
__global__ __launch_bounds__(TPB, 7) void et_pair_kernel(
    const float* __restrict__ x, const float* __restrict__ W,
    float* __restrict__ out)
{
    // x duplicated pairs: sxd[buf][row][k] = (x[row,k], x[row,k]); 2 x 4KB
    __shared__ __align__(16) unsigned long long sxd[2][RPB][K0];
    __shared__ float sred[TPB / 32];
    __shared__ float s_c;

    const int tid  = threadIdx.x;
    const int lane = tid & 31;
    const int warp = tid >> 5;
    const int o0   = blockIdx.x * CPB + tid * CPT;

    const int r = tid >> 2, h = tid & 3;   // x-chunk owner: row r, floats [4h,4h+4)

    int t = blockIdx.y;                    // first tile

    // ---- issue tile-0 x prefetch early (4 floats) ----
    float4 pf = *(reinterpret_cast<const float4*>(
                      x + (size_t)(t * RPB + r) * DIN) + h);

    // ---- c = dot(W[0,16:], x[0,16:]) (f32 vectorized + warp reduce) ----
    {
        const float4* x4 = reinterpret_cast<const float4*>(x);
        const float4* w4 = reinterpret_cast<const float4*>(W);
        float acc = 0.0f;
#pragma unroll
        for (int k = 0; k < 8; ++k) {
            int fidx = 4 + tid + k * TPB;          // float4 index, [4,1024)
            if (fidx < DIN / 4) {
                float4 xv = x4[fidx];
                float4 wv = w4[fidx];
                acc += xv.x * wv.x + xv.y * wv.y + xv.z * wv.z + xv.w * wv.w;
            }
        }
#pragma unroll
        for (int off = 16; off > 0; off >>= 1)
            acc += __shfl_xor_sync(0xFFFFFFFFu, acc, off);
        if (lane == 0) sred[warp] = acc;
    }

    // ---- W column pair packed across columns: w2[k] = (W[o0,k], W[o0+1,k]) ----
    unsigned long long w2[K0];
    {
        const float4* wp0 = reinterpret_cast<const float4*>(W + (size_t)o0 * DIN);
        const float4* wp1 = reinterpret_cast<const float4*>(W + (size_t)(o0 + 1) * DIN);
#pragma unroll
        for (int q = 0; q < 4; ++q) {
            float4 a = wp0[q], b = wp1[q];
            w2[4 * q + 0] = pack2(a.x, b.x);
            w2[4 * q + 1] = pack2(a.y, b.y);
            w2[4 * q + 2] = pack2(a.z, b.z);
            w2[4 * q + 3] = pack2(a.w, b.w);
        }
    }

    // commit tile-0 x (duplicated lanes) + finish c reduction
    {
        ulonglong2* dst = reinterpret_cast<ulonglong2*>(&sxd[0][r][4 * h]);
        dst[0] = make_ulonglong2(pack2(pf.x, pf.x), pack2(pf.y, pf.y));
        dst[1] = make_ulonglong2(pack2(pf.z, pf.z), pack2(pf.w, pf.w));
    }
    __syncthreads();
    if (tid == 0) {
        float c = 0.0f;
#pragma unroll
        for (int i = 0; i < TPB / 32; ++i) c += sred[i];
        s_c = c;
    }
    __syncthreads();

    const unsigned long long cinit = pack2(s_c, s_c);   // both lanes carry +c
    int buf = 0;

    // ---- persistent tile loop: exactly NTILES/YBLKS = 4 tiles ----
    for (;;) {
        const int tn = t + YBLKS;
        const bool more = tn < NTILES;

        float4 pf2;
        if (more)
            pf2 = *(reinterpret_cast<const float4*>(
                        x + (size_t)(tn * RPB + r) * DIN) + h);

        size_t outIdx = (size_t)t * RPB * DOUT + o0;
#pragma unroll 4
        for (int rr = 0; rr < RPB; ++rr) {
            unsigned long long acc = cinit;
            const ulonglong2* xr = reinterpret_cast<const ulonglong2*>(sxd[buf][rr]);
#pragma unroll
            for (int q = 0; q < 8; ++q) {
                ulonglong2 xv = xr[q];          // LDS.128 broadcast, 2 dup pairs
                acc = ffma2(xv.x, w2[2 * q],     acc);
                acc = ffma2(xv.y, w2[2 * q + 1], acc);
            }
            *reinterpret_cast<unsigned long long*>(out + outIdx) = acc; // STG.64
            outIdx += DOUT;
        }

        if (!more) break;

        // stage next tile into the other buffer, one barrier before consuming
        {
            ulonglong2* dst = reinterpret_cast<ulonglong2*>(&sxd[buf ^ 1][r][4 * h]);
            dst[0] = make_ulonglong2(pack2(pf2.x, pf2.x), pack2(pf2.y, pf2.y));
            dst[1] = make_ulonglong2(pack2(pf2.z, pf2.z), pack2(pf2.w, pf2.w));
        }
        __syncthreads();
        buf ^= 1;
        t = tn;
    }
}

extern "C" void kernel_launch(void* const* d_in, const int* in_sizes, int n_in,
                              void* d_out, int out_size) {
    const float* x = (const float*)d_in[0];   // (4,2048,4096) f32
    const float* W = (const float*)d_in[1];   // (4096,4096)  f32
    float* out = (float*)d_out;               // (4,2048,4096) f32

    dim3 grid(DOUT / CPB, YBLKS);             // (16, 64) = 1024 blocks, ~1 wave @7/SM
    et_pair_kernel<<<grid, TPB>>>(x, W, out);
}

// round 8
// speedup vs baseline: 1.1562x; 1.1562x over previous
#include <cuda_runtime.h>
#include <cstdint>

#define K0     16
#define DIN    4096
#define DOUT   4096
#define NROWS  8192
#define TPB    128
#define CPT    4                    // columns per thread
#define CPB    (TPB * CPT)          // 512 columns per column-group
#define NCG    (DOUT / CPB)         // 8 column groups
#define RPI    16                   // rows per work item
#define NRT    (NROWS / RPI)        // 512 row tiles
#define N_ITEMS (NCG * NRT)         // 4096 work items
#define NBLK   740                  // 148 SMs x 5 resident blocks

typedef unsigned long long ull;

__device__ unsigned g_ctr  = 0;     // work-stealing counter
__device__ unsigned g_done = 0;     // finished-block counter (resets g_ctr)

// ---- packed f32x2 helpers (Blackwell FFMA2 path, PTX-only) ----
__device__ __forceinline__ ull ffma2(ull a, ull b, ull c) {
    ull d;
    asm("fma.rn.f32x2 %0, %1, %2, %3;" : "=l"(d) : "l"(a), "l"(b), "l"(c));
    return d;
}
__device__ __forceinline__ ull pack2(float lo, float hi) {
    ull r;
    asm("mov.b64 %0, {%1, %2};" : "=l"(r) : "f"(lo), "f"(hi));
    return r;
}
__device__ __forceinline__ float hsum2(ull v) {
    float lo, hi;
    asm("mov.b64 {%0, %1}, %2;" : "=f"(lo), "=f"(hi) : "l"(v));
    return lo + hi;
}

__device__ __forceinline__ void load_w(ull (&w)[CPT][8], const float* __restrict__ W,
                                       int o0) {
#pragma unroll
    for (int c = 0; c < CPT; ++c) {
        const ulonglong2* wp =
            reinterpret_cast<const ulonglong2*>(W + (size_t)(o0 + c) * DIN);
#pragma unroll
        for (int hh = 0; hh < 4; ++hh) {
            ulonglong2 v = wp[hh];
            w[c][2 * hh]     = v.x;
            w[c][2 * hh + 1] = v.y;
        }
    }
}

// out[r,o] = c + sum_{k<16} x[r,k]*W[o,k]
// (tstat >= 0 > TAU so the reference mask is identically "active".)
// Persistent work-stealing: 740 blocks pull (colgroup, 16-row) items off a
// global counter; W regs persist per colgroup; x prefetch + steal pipelined.
__global__ __launch_bounds__(TPB, 5) void et_steal_kernel(
    const float* __restrict__ x, const float* __restrict__ W,
    float* __restrict__ out)
{
    __shared__ __align__(16) ull sx[2][RPI][K0 / 2];   // 2 x 1KB x-tiles
    __shared__ float sred[TPB / 32];
    __shared__ float s_c;
    __shared__ unsigned s_id[2];

    const int tid  = threadIdx.x;
    const int lane = tid & 31;
    const int warp = tid >> 5;
    const int colT = tid * CPT;
    const int r = tid >> 2, h = tid & 3;   // x staging: row r (<16), chunk h (tid<64)

    // ---- steal first item + c partial ----
    if (tid == 0) s_id[0] = atomicAdd(&g_ctr, 1u);
    {
        const float4* x4 = reinterpret_cast<const float4*>(x);
        const float4* w4 = reinterpret_cast<const float4*>(W);
        float acc = 0.0f;
#pragma unroll
        for (int k = 0; k < 8; ++k) {
            int fidx = 4 + tid + k * TPB;          // float4 index, [4,1024)
            if (fidx < DIN / 4) {
                float4 xv = x4[fidx];
                float4 wv = w4[fidx];
                acc += xv.x * wv.x + xv.y * wv.y + xv.z * wv.z + xv.w * wv.w;
            }
        }
#pragma unroll
        for (int off = 16; off > 0; off >>= 1)
            acc += __shfl_xor_sync(0xFFFFFFFFu, acc, off);
        if (lane == 0) sred[warp] = acc;
    }
    __syncthreads();

    unsigned id = s_id[0];                  // < N_ITEMS always (740 < 4096)
    int cg = (int)(id >> 9);                // id / NRT
    int rt = (int)(id & (NRT - 1));

    ull w[CPT][8];
    load_w(w, W, cg * CPB + colT);

    float4 pf;
    if (tid < RPI * 4)
        pf = *(reinterpret_cast<const float4*>(
                   x + (size_t)(rt * RPI + r) * DIN) + h);

    if (tid == 0) {
        float cc = 0.0f;
#pragma unroll
        for (int i = 0; i < TPB / 32; ++i) cc += sred[i];
        s_c = cc;
        s_id[1] = atomicAdd(&g_ctr, 1u);    // steal item 1
    }
    if (tid < RPI * 4)
        *(reinterpret_cast<float4*>(sx[0][r]) + h) = pf;
    __syncthreads();

    const ull cinit = pack2(s_c, 0.0f);     // lane0 carries +c
    unsigned nid = s_id[1];
    if (nid < N_ITEMS && tid < RPI * 4) {   // prefetch item-1 x
        int nrt = (int)(nid & (NRT - 1));
        pf = *(reinterpret_cast<const float4*>(
                   x + (size_t)(nrt * RPI + r) * DIN) + h);
    }

    int cur = 0, par = 0;

    // ---- main stealing loop; one barrier per item ----
    for (;;) {
        if (tid == 0) s_id[par] = atomicAdd(&g_ctr, 1u);   // steal item k+2

        // compute current item from sx[cur]
        size_t outIdx = (size_t)(rt * RPI) * DOUT + cg * CPB + colT;
#pragma unroll 4
        for (int rr = 0; rr < RPI; ++rr) {
            ull a0 = cinit, a1 = cinit, a2 = cinit, a3 = cinit;
            const ulonglong2* xr = reinterpret_cast<const ulonglong2*>(sx[cur][rr]);
#pragma unroll
            for (int q = 0; q < 4; ++q) {
                ulonglong2 xv = xr[q];          // LDS.128 broadcast
                a0 = ffma2(xv.x, w[0][2 * q], a0);
                a1 = ffma2(xv.x, w[1][2 * q], a1);
                a2 = ffma2(xv.x, w[2][2 * q], a2);
                a3 = ffma2(xv.x, w[3][2 * q], a3);
                a0 = ffma2(xv.y, w[0][2 * q + 1], a0);
                a1 = ffma2(xv.y, w[1][2 * q + 1], a1);
                a2 = ffma2(xv.y, w[2][2 * q + 1], a2);
                a3 = ffma2(xv.y, w[3][2 * q + 1], a3);
            }
            float4 o;
            o.x = hsum2(a0);
            o.y = hsum2(a1);
            o.z = hsum2(a2);
            o.w = hsum2(a3);
            *reinterpret_cast<float4*>(out + outIdx) = o;   // STG.128
            outIdx += DOUT;
        }

        if (nid >= N_ITEMS) break;

        // stage next item's x (pf was loaded during the compute above)
        if (tid < RPI * 4)
            *(reinterpret_cast<float4*>(sx[cur ^ 1][r]) + h) = pf;

        int ncg = (int)(nid >> 9);
        if (ncg != cg) {                      // rare: colgroup boundary
            cg = ncg;
            load_w(w, W, cg * CPB + colT);
        }
        rt = (int)(nid & (NRT - 1));

        __syncthreads();                      // STS + s_id visible; buffers rotate
        cur ^= 1;

        nid = s_id[par];                      // item k+2's id
        par ^= 1;
        if (nid < N_ITEMS && tid < RPI * 4) { // prefetch its x under next compute
            int nrt = (int)(nid & (NRT - 1));
            pf = *(reinterpret_cast<const float4*>(
                       x + (size_t)(nrt * RPI + r) * DIN) + h);
        }
    }

    // ---- last block resets counters for the next (graph-replayed) launch ----
    __syncthreads();
    if (tid == 0) {
        __threadfence();
        if (atomicAdd(&g_done, 1u) == NBLK - 1) {
            g_ctr  = 0;
            g_done = 0;
            __threadfence();
        }
    }
}

extern "C" void kernel_launch(void* const* d_in, const int* in_sizes, int n_in,
                              void* d_out, int out_size) {
    const float* x = (const float*)d_in[0];   // (4,2048,4096) f32
    const float* W = (const float*)d_in[1];   // (4096,4096)  f32
    float* out = (float*)d_out;               // (4,2048,4096) f32

    et_steal_kernel<<<NBLK, TPB>>>(x, W, out);
}

// round 9
// speedup vs baseline: 1.2003x; 1.0382x over previous
#include <cuda_runtime.h>
#include <cstdint>

#define K0    16
#define DIN   4096
#define DOUT  4096
#define NROWS 8192
#define TPB   128
#define NBLK  736                  // ~5 blocks/SM, one wave
#define NWARP (NBLK * 4)           // 2944 warps
#define NCG   32                   // DOUT / 128 column groups (one per warp)
#define WPC   (NWARP / NCG)        // 92 row-slices per colgroup
#define CPT   4                    // columns per lane

typedef unsigned long long ull;

// ---- packed f32x2 helpers (Blackwell FFMA2 path, PTX-only) ----
__device__ __forceinline__ ull ffma2(ull a, ull b, ull c) {
    ull d;
    asm("fma.rn.f32x2 %0, %1, %2, %3;" : "=l"(d) : "l"(a), "l"(b), "l"(c));
    return d;
}
__device__ __forceinline__ ull pack2(float lo, float hi) {
    ull r;
    asm("mov.b64 %0, {%1, %2};" : "=l"(r) : "f"(lo), "f"(hi));
    return r;
}
__device__ __forceinline__ float hsum2(ull v) {      // mov.b64 unpack is free
    float lo, hi;
    asm("mov.b64 {%0, %1}, %2;" : "=f"(lo), "=f"(hi) : "l"(v));
    return lo + hi;
}

// out[r,o] = c + sum_{k<16} x[r,k]*W[o,k]
// (tstat >= 0 > TAU so the reference's mask is identically "active".)
// Warp-independent schedule: each warp owns 128 columns and a strided row
// slice; x rows are LDG-broadcast (64B, L1/L2 resident) -- no smem staging,
// no per-tile barriers, no atomics. One barrier total (the c reduction).
__global__ __launch_bounds__(TPB, 5) void et_warp_kernel(
    const float* __restrict__ x, const float* __restrict__ W,
    float* __restrict__ out)
{
    __shared__ float sred[TPB / 32];
    __shared__ float s_c;

    const int tid  = threadIdx.x;
    const int lane = tid & 31;
    const int warp = tid >> 5;

    // ---- c = dot(W[0,16:], x[0,16:]) (vectorized f32 + warp/block reduce) ----
    {
        const float4* x4 = reinterpret_cast<const float4*>(x);
        const float4* w4 = reinterpret_cast<const float4*>(W);
        float acc = 0.0f;
#pragma unroll
        for (int k = 0; k < 8; ++k) {
            int fidx = 4 + tid + k * TPB;          // float4 index, [4,1024)
            if (fidx < DIN / 4) {
                float4 xv = x4[fidx];
                float4 wv = w4[fidx];
                acc += xv.x * wv.x + xv.y * wv.y + xv.z * wv.z + xv.w * wv.w;
            }
        }
#pragma unroll
        for (int off = 16; off > 0; off >>= 1)
            acc += __shfl_xor_sync(0xFFFFFFFFu, acc, off);
        if (lane == 0) sred[warp] = acc;
    }
    __syncthreads();
    if (tid == 0) {
        float cc = 0.0f;
#pragma unroll
        for (int i = 0; i < TPB / 32; ++i) cc += sred[i];
        s_c = cc;
    }
    __syncthreads();
    const ull cinit = pack2(s_c, 0.0f);      // lane0 of each pair carries +c

    // ---- warp work assignment ----
    const int gw = blockIdx.x * (TPB / 32) + warp;   // 0..2943
    const int cg = gw & (NCG - 1);                   // column group (128 cols)
    const int j  = gw >> 5;                          // row slice 0..91
    const int o0 = (cg << 7) + (lane << 2);          // this lane's 4 columns

    // ---- W column-prefixes into registers (once per warp) ----
    ull w[CPT][8];
#pragma unroll
    for (int c = 0; c < CPT; ++c) {
        const ulonglong2* wp =
            reinterpret_cast<const ulonglong2*>(W + (size_t)(o0 + c) * DIN);
#pragma unroll
        for (int hh = 0; hh < 4; ++hh) {
            ulonglong2 v = wp[hh];
            w[c][2 * hh]     = v.x;
            w[c][2 * hh + 1] = v.y;
        }
    }

    // ---- row loop: rows j, j+92, ... ; 1-row register prefetch ----
    int r = j;
    ulonglong2 pre0, pre1, pre2, pre3;
    {
        const ulonglong2* xp = reinterpret_cast<const ulonglong2*>(
                                   x + (size_t)r * DIN);
        pre0 = xp[0]; pre1 = xp[1]; pre2 = xp[2]; pre3 = xp[3];
    }

    while (r < NROWS) {
        const int rn = r + WPC;
        ulonglong2 c0 = pre0, c1 = pre1, c2 = pre2, c3 = pre3;
        if (rn < NROWS) {
            const ulonglong2* xp = reinterpret_cast<const ulonglong2*>(
                                       x + (size_t)rn * DIN);
            pre0 = xp[0]; pre1 = xp[1]; pre2 = xp[2]; pre3 = xp[3];
        }

        ull a0 = cinit, a1 = cinit, a2 = cinit, a3 = cinit;
#define STEP(v)                         \
        a0 = ffma2((v), w[0][_q], a0);  \
        a1 = ffma2((v), w[1][_q], a1);  \
        a2 = ffma2((v), w[2][_q], a2);  \
        a3 = ffma2((v), w[3][_q], a3);  _q++;
        {
            int _q = 0;
            STEP(c0.x) STEP(c0.y) STEP(c1.x) STEP(c1.y)
            STEP(c2.x) STEP(c2.y) STEP(c3.x) STEP(c3.y)
        }
#undef STEP

        float4 o;
        o.x = hsum2(a0);
        o.y = hsum2(a1);
        o.z = hsum2(a2);
        o.w = hsum2(a3);
        *reinterpret_cast<float4*>(out + (size_t)r * DOUT + o0) = o; // STG.128

        r = rn;
    }
}

extern "C" void kernel_launch(void* const* d_in, const int* in_sizes, int n_in,
                              void* d_out, int out_size) {
    const float* x = (const float*)d_in[0];   // (4,2048,4096) f32
    const float* W = (const float*)d_in[1];   // (4096,4096)  f32
    float* out = (float*)d_out;               // (4,2048,4096) f32

    et_warp_kernel<<<NBLK, TPB>>>(x, W, out);
}

// round 10
// speedup vs baseline: 1.6919x; 1.4095x over previous
#include <cuda_runtime.h>
#include <cstdint>

#define K0     16
#define DIN    4096
#define DOUT   4096
#define NROWS  8192
#define TPB    128
#define CPT    4                    // columns per thread
#define CPB    (TPB * CPT)          // 512 columns per block
#define RPB    32                   // rows per tile
#define NTILES (NROWS / RPB)        // 256
#define YBLKS  111                  // grid (8,111) = 888 blocks = 148 SMs x 6

typedef unsigned long long ull;

// ---- packed f32x2 helpers (Blackwell FFMA2 path, PTX-only) ----
__device__ __forceinline__ ull ffma2(ull a, ull b, ull c) {
    ull d;
    asm("fma.rn.f32x2 %0, %1, %2, %3;" : "=l"(d) : "l"(a), "l"(b), "l"(c));
    return d;
}
__device__ __forceinline__ ull pack2(float lo, float hi) {
    ull r;
    asm("mov.b64 %0, {%1, %2};" : "=l"(r) : "f"(lo), "f"(hi));
    return r;
}
__device__ __forceinline__ float hsum2(ull v) {
    float lo, hi;
    asm("mov.b64 {%0, %1}, %2;" : "=f"(lo), "=f"(hi) : "l"(v));
    return lo + hi;
}

// cp.async 16B: GMEM -> SMEM without registers
__device__ __forceinline__ void cp_async16(void* smem_dst, const void* gsrc) {
    unsigned saddr = (unsigned)__cvta_generic_to_shared(smem_dst);
    asm volatile("cp.async.ca.shared.global [%0], [%1], 16;"
                 :: "r"(saddr), "l"(gsrc) : "memory");
}
__device__ __forceinline__ void cp_async_commit() {
    asm volatile("cp.async.commit_group;" ::: "memory");
}
__device__ __forceinline__ void cp_async_wait0() {
    asm volatile("cp.async.wait_group 0;" ::: "memory");
}

// out[r,o] = c + sum_{k<16} x[r,k]*W[o,k]
// (tstat >= 0 > TAU, so the reference's mask is identically "active";
//  the op collapses to a rank-16 update plus the scalar c.)
// R4 dataflow (smem x tile + W in regs + STG.128) with: cp.async prefetch
// (no prefetch registers), 6 blocks/SM, exactly-one-wave grid.
__global__ __launch_bounds__(TPB, 6) void et_cpasync_kernel(
    const float* __restrict__ x, const float* __restrict__ W,
    float* __restrict__ out)
{
    __shared__ __align__(16) ull sx[2][RPB][K0 / 2];   // 2 x 2KB x-tiles
    __shared__ float sred[TPB / 32];
    __shared__ float s_c;

    const int tid  = threadIdx.x;
    const int lane = tid & 31;
    const int warp = tid >> 5;
    const int o0   = blockIdx.x * CPB + tid * CPT;
    const int r = tid >> 2, h = tid & 3;   // x staging: row r, 16B chunk h
    const int by = blockIdx.y;

    // ---- issue tile-0 prefetch first (max overlap with prologue) ----
    cp_async16(&sx[0][r][2 * h],
               x + (size_t)(by * RPB + r) * DIN + 4 * h);
    cp_async_commit();

    // ---- c = dot(W[0,16:], x[0,16:]) (vectorized f32 + warp reduce) ----
    {
        const float4* x4 = reinterpret_cast<const float4*>(x);
        const float4* w4 = reinterpret_cast<const float4*>(W);
        float acc = 0.0f;
#pragma unroll
        for (int k = 0; k < 8; ++k) {
            int fidx = 4 + tid + k * TPB;          // float4 index, [4,1024)
            if (fidx < DIN / 4) {
                float4 xv = x4[fidx];
                float4 wv = w4[fidx];
                acc += xv.x * wv.x + xv.y * wv.y + xv.z * wv.z + xv.w * wv.w;
            }
        }
#pragma unroll
        for (int off = 16; off > 0; off >>= 1)
            acc += __shfl_xor_sync(0xFFFFFFFFu, acc, off);
        if (lane == 0) sred[warp] = acc;
    }

    // ---- W column-prefixes into registers (lives whole kernel) ----
    ull w[CPT][8];
#pragma unroll
    for (int c = 0; c < CPT; ++c) {
        const ulonglong2* wp =
            reinterpret_cast<const ulonglong2*>(W + (size_t)(o0 + c) * DIN);
#pragma unroll
        for (int hh = 0; hh < 4; ++hh) {
            ulonglong2 v = wp[hh];
            w[c][2 * hh]     = v.x;
            w[c][2 * hh + 1] = v.y;
        }
    }

    __syncthreads();                       // sred ready
    if (tid == 0) {
        float cc = 0.0f;
#pragma unroll
        for (int i = 0; i < TPB / 32; ++i) cc += sred[i];
        s_c = cc;
    }
    cp_async_wait0();                      // own tile-0 copies done
    __syncthreads();                       // s_c + all tile-0 copies visible

    const ull cinit = pack2(s_c, 0.0f);    // lane0 of each pair carries +c
    int cur = 0;

    // ---- tile loop: tiles by, by+111, by+222 ----
    for (int t = by; t < NTILES; t += YBLKS, cur ^= 1) {
        const int tn = t + YBLKS;
        const bool more = tn < NTILES;

        if (more) {                        // stream next tile GMEM->SMEM
            cp_async16(&sx[cur ^ 1][r][2 * h],
                       x + (size_t)(tn * RPB + r) * DIN + 4 * h);
            cp_async_commit();
        }

        size_t outIdx = (size_t)(t * RPB) * DOUT + o0;
#pragma unroll 4
        for (int rr = 0; rr < RPB; ++rr) {
            ull a0 = cinit, a1 = cinit, a2 = cinit, a3 = cinit;
            const ulonglong2* xr = reinterpret_cast<const ulonglong2*>(sx[cur][rr]);
#pragma unroll
            for (int q = 0; q < 4; ++q) {
                ulonglong2 xv = xr[q];          // LDS.128 broadcast
                a0 = ffma2(xv.x, w[0][2 * q], a0);
                a1 = ffma2(xv.x, w[1][2 * q], a1);
                a2 = ffma2(xv.x, w[2][2 * q], a2);
                a3 = ffma2(xv.x, w[3][2 * q], a3);
                a0 = ffma2(xv.y, w[0][2 * q + 1], a0);
                a1 = ffma2(xv.y, w[1][2 * q + 1], a1);
                a2 = ffma2(xv.y, w[2][2 * q + 1], a2);
                a3 = ffma2(xv.y, w[3][2 * q + 1], a3);
            }
            float4 o;
            o.x = hsum2(a0);
            o.y = hsum2(a1);
            o.z = hsum2(a2);
            o.w = hsum2(a3);
            *reinterpret_cast<float4*>(out + outIdx) = o;   // STG.128
            outIdx += DOUT;
        }

        if (more) {
            cp_async_wait0();              // next tile landed
            __syncthreads();               // visible to all warps
        }
    }
}

extern "C" void kernel_launch(void* const* d_in, const int* in_sizes, int n_in,
                              void* d_out, int out_size) {
    const float* x = (const float*)d_in[0];   // (4,2048,4096) f32
    const float* W = (const float*)d_in[1];   // (4096,4096)  f32
    float* out = (float*)d_out;               // (4,2048,4096) f32

    dim3 grid(DOUT / CPB, YBLKS);             // (8, 111) = 888 blocks = one wave @6/SM
    et_cpasync_kernel<<<grid, TPB>>>(x, W, out);
}

// round 12
// speedup vs baseline: 1.8570x; 1.0976x over previous
#include <cuda_runtime.h>
#include <cuda_bf16.h>
#include <cstdint>
#include <cstring>

#define DIN   4096
#define DOUT  4096
#define NROWS 8192
#define TPB   128
#define BLK_COLS 128   // 4 warps x 4 n-slices x 8 cols
#define BLK_ROWS 128   // 8 m-tiles of 16 rows
#define NSLICE 4

// out[r,o] = c + sum_{k<16} x[r,k]*W[o,k]
// (tstat = |y1|/sqrt(s2/16) >= 0 > TAU, so "passed" is identically false and
//  the reference collapses to this rank-16 update plus the scalar c.)
// Tensor path: legacy mma.sync m16n8k16 bf16 (HMMA, supported on plain sm_103 —
// tcgen05 is rejected by this toolchain). Precision via bf16 hi/lo K-split:
// x*W ~= x_hi*W_hi + x_lo*W_hi + x_hi*W_lo  (error ~ x_lo*W_lo ~ 2^-18 rel).
// Accumulators live in registers, init to c; stores go straight from D frags.

__device__ __forceinline__ void mma16816(float& d0, float& d1, float& d2, float& d3,
                                         unsigned a0, unsigned a1, unsigned a2,
                                         unsigned a3, unsigned b0, unsigned b1) {
    asm volatile(
        "mma.sync.aligned.m16n8k16.row.col.f32.bf16.bf16.f32 "
        "{%0,%1,%2,%3}, {%4,%5,%6,%7}, {%8,%9}, {%0,%1,%2,%3};"
        : "+f"(d0), "+f"(d1), "+f"(d2), "+f"(d3)
        : "r"(a0), "r"(a1), "r"(a2), "r"(a3), "r"(b0), "r"(b1));
}

// split a float2 into packed bf16x2 hi + packed bf16x2 residual (lo)
__device__ __forceinline__ void split2(float2 f, unsigned& hi, unsigned& lo) {
    __nv_bfloat162 h = __floats2bfloat162_rn(f.x, f.y);   // x -> low half
    memcpy(&hi, &h, 4);
    float rx = f.x - __bfloat162float(h.x);
    float ry = f.y - __bfloat162float(h.y);
    __nv_bfloat162 l = __floats2bfloat162_rn(rx, ry);
    memcpy(&lo, &l, 4);
}

__global__ __launch_bounds__(TPB) void et_hmma_kernel(
    const float* __restrict__ x, const float* __restrict__ W,
    float* __restrict__ out)
{
    __shared__ float sred[TPB / 32];
    __shared__ float s_c;

    const int tid  = threadIdx.x;
    const int lane = tid & 31;
    const int wid  = tid >> 5;
    const int g    = lane >> 2;          // fragment group id 0..7 (row / n)
    const int t2   = (lane & 3) * 2;     // fragment k/col base 0,2,4,6

    // ---- c = dot(W[0,16:], x[0,16:]) (vectorized f32 + warp/block reduce) ----
    {
        const float4* x4 = reinterpret_cast<const float4*>(x);
        const float4* w4 = reinterpret_cast<const float4*>(W);
        float acc = 0.0f;
#pragma unroll
        for (int k = 0; k < 8; ++k) {
            int fidx = 4 + tid + k * TPB;          // float4 index, [4,1024)
            if (fidx < DIN / 4) {
                float4 xv = x4[fidx];
                float4 wv = w4[fidx];
                acc += xv.x * wv.x + xv.y * wv.y + xv.z * wv.z + xv.w * wv.w;
            }
        }
#pragma unroll
        for (int off = 16; off > 0; off >>= 1)
            acc += __shfl_xor_sync(0xFFFFFFFFu, acc, off);
        if (lane == 0) sred[wid] = acc;
    }
    __syncthreads();
    if (tid == 0) s_c = sred[0] + sred[1] + sred[2] + sred[3];
    __syncthreads();
    const float cval = s_c;

    // ---- B fragments: this warp's 32 W-columns (4 slices x 8), hi+lo ----
    const int r0 = blockIdx.y * BLK_ROWS;
    const int o0 = blockIdx.x * BLK_COLS + wid * (NSLICE * 8);

    unsigned bh[NSLICE][2], bl[NSLICE][2];
#pragma unroll
    for (int s = 0; s < NSLICE; ++s) {
        const float* wr = W + (size_t)(o0 + s * 8 + g) * DIN;   // n = o0+s*8+g
        float2 w0 = *reinterpret_cast<const float2*>(wr + t2);      // k t2,t2+1
        float2 w1 = *reinterpret_cast<const float2*>(wr + t2 + 8);  // k +8
        split2(w0, bh[s][0], bl[s][0]);
        split2(w1, bh[s][1], bl[s][1]);
    }

    // ---- M loop over 8 tiles of 16 rows; software prefetch of A loads ----
    float2 p00, p10, p01, p11;
    {
        const float* xr0 = x + (size_t)(r0 + g) * DIN;
        const float* xr1 = xr0 + 8 * DIN;
        p00 = *reinterpret_cast<const float2*>(xr0 + t2);
        p10 = *reinterpret_cast<const float2*>(xr1 + t2);
        p01 = *reinterpret_cast<const float2*>(xr0 + t2 + 8);
        p11 = *reinterpret_cast<const float2*>(xr1 + t2 + 8);
    }

#pragma unroll
    for (int mt = 0; mt < BLK_ROWS; mt += 16) {
        float2 a00 = p00, a10 = p10, a01 = p01, a11 = p11;
        if (mt + 16 < BLK_ROWS) {       // prefetch next tile's A data
            const float* xr0 = x + (size_t)(r0 + mt + 16 + g) * DIN;
            const float* xr1 = xr0 + 8 * DIN;
            p00 = *reinterpret_cast<const float2*>(xr0 + t2);
            p10 = *reinterpret_cast<const float2*>(xr1 + t2);
            p01 = *reinterpret_cast<const float2*>(xr0 + t2 + 8);
            p11 = *reinterpret_cast<const float2*>(xr1 + t2 + 8);
        }

        // A fragments: a0=(row g,k t2) a1=(row g+8) a2=(row g,k t2+8) a3=(row g+8)
        unsigned ah[4], al[4];
        split2(a00, ah[0], al[0]);
        split2(a10, ah[1], al[1]);
        split2(a01, ah[2], al[2]);
        split2(a11, ah[3], al[3]);

        const int row = r0 + mt + g;
#pragma unroll
        for (int s = 0; s < NSLICE; ++s) {
            float d0 = cval, d1 = cval, d2 = cval, d3 = cval;
            mma16816(d0, d1, d2, d3, ah[0], ah[1], ah[2], ah[3], bh[s][0], bh[s][1]);
            mma16816(d0, d1, d2, d3, al[0], al[1], al[2], al[3], bh[s][0], bh[s][1]);
            mma16816(d0, d1, d2, d3, ah[0], ah[1], ah[2], ah[3], bl[s][0], bl[s][1]);

            // D frag: (d0,d1)@(row, col t2) ; (d2,d3)@(row+8, col t2)
            float* po = out + (size_t)row * DOUT + (o0 + s * 8 + t2);
            *reinterpret_cast<float2*>(po)              = make_float2(d0, d1);
            *reinterpret_cast<float2*>(po + 8 * DOUT)   = make_float2(d2, d3);
        }
    }
}

extern "C" void kernel_launch(void* const* d_in, const int* in_sizes, int n_in,
                              void* d_out, int out_size) {
    const float* x = (const float*)d_in[0];   // (4,2048,4096) f32
    const float* W = (const float*)d_in[1];   // (4096,4096)  f32
    float* out = (float*)d_out;               // (4,2048,4096) f32

    dim3 grid(DOUT / BLK_COLS, NROWS / BLK_ROWS);   // (32, 64) = 2048 blocks
    et_hmma_kernel<<<grid, TPB>>>(x, W, out);
}